// round 8
// baseline (speedup 1.0000x reference)
#include <cuda_runtime.h>

// Problem constants: b=2, s=4096, h=16, p=n=64, BLOCK_LEN=64
#define NB   2
#define NH   16
#define NC   64
#define PADS 64   // straight tiles
#define PADT 68   // transposed tiles (mult of 4; rotated stores <=2-way)

// Scratch (__device__ globals; allocation-free rule)
__device__ float g_states[NB*NH*NC*4096];  // chunk states [n][p]; scanned in place
__device__ float g_G[NB*NH*NC*4096];       // masked decay-weighted Gt [s][l]
__device__ float g_tot[NB*NH*NC];          // per-chunk A totals

// ---------------------------------------------------------------------------
// Kernel G1: Gt[s][l] = (l>=s) ? sum_n (B[s][n]*em[s]) * (C[l][n]*ecl[l]) : 0
//   em=exp(A-cs), ecl=exp(cs) folded into the transposed tiles at load.
// 128 threads, 8x4 micro-tile, 2 smem tiles (34.8KB) -> 6 CTAs/SM.
// ---------------------------------------------------------------------------
__global__ void __launch_bounds__(128, 6) gemm1_kernel(
    const float* __restrict__ A, const float* __restrict__ B,
    const float* __restrict__ C)
{
    __shared__ float Bte[64*PADT];   // B^T * em  : [n][s]
    __shared__ float Cte[64*PADT];   // C^T * ecl : [n][l]
    __shared__ float s_cs[64], s_em[64], s_ecl[64];

    const int c = blockIdx.x, h = blockIdx.y, b = blockIdx.z;
    const int bhc = (b*NH + h)*NC + c;
    const int tid = threadIdx.x;
    const int tx = tid & 15, ty = tid >> 4;
    const size_t base = ((size_t)((b*4096 + c*64)*NH + h))*64;
    const int col4 = tx*4;

    // inclusive cumsum of A (threads 0..63)
    if (tid < 64) {
        const float av = A[(size_t)(b*4096 + c*64 + tid)*NH + h];
        float v = av;
        #pragma unroll
        for (int o = 1; o < 32; o <<= 1) {
            float t = __shfl_up_sync(0xffffffffu, v, o);
            if ((tid & 31) >= o) v += t;
        }
        s_cs[tid] = v;
        s_em[tid] = av;
    }
    __syncthreads();
    if (tid >= 32 && tid < 64) s_cs[tid] += s_cs[31];
    __syncthreads();
    if (tid < 64) {
        const float csl = s_cs[tid];
        s_ecl[tid] = __expf(csl);
        s_em[tid]  = __expf(s_em[tid] - csl);
        if (tid == 63) g_tot[bhc] = csl;   // chunk total
    }
    __syncthreads();

    // transposed scaled loads (rotated scalar stores, <=2-way conflicts)
    #pragma unroll
    for (int i = 0; i < 8; i++) {
        const int row = i*8 + ty;
        const size_t g = base + (size_t)row*1024 + col4;
        float4 bf = *(const float4*)(B + g);
        float4 cf = *(const float4*)(C + g);
        const float em = s_em[row], e = s_ecl[row];
        float bs[4] = {bf.x*em, bf.y*em, bf.z*em, bf.w*em};
        float cs[4] = {cf.x*e,  cf.y*e,  cf.z*e,  cf.w*e};
        #pragma unroll
        for (int q = 0; q < 4; q++) {
            const int eq = (q + (tx >> 1)) & 3;
            Bte[(col4 + eq)*PADT + row] = bs[eq];
            Cte[(col4 + eq)*PADT + row] = cs[eq];
        }
    }
    __syncthreads();

    const int rb = ty*8, cb = col4;
    float acc[8][4] = {};
    #pragma unroll 4
    for (int k = 0; k < 64; k++) {
        float a[8], bb[4];
        *(float4*)(a)     = *(const float4*)(Bte + k*PADT + rb);
        *(float4*)(a + 4) = *(const float4*)(Bte + k*PADT + rb + 4);
        *(float4*)(bb)    = *(const float4*)(Cte + k*PADT + cb);
        #pragma unroll
        for (int i = 0; i < 8; i++)
            #pragma unroll
            for (int j = 0; j < 4; j++)
                acc[i][j] += a[i] * bb[j];
    }

    float* gt = g_G + (size_t)bhc*4096;
    #pragma unroll
    for (int i = 0; i < 8; i++) {
        const int s = rb + i;
        float4 v;
        v.x = (cb + 0 >= s) ? acc[i][0] : 0.f;
        v.y = (cb + 1 >= s) ? acc[i][1] : 0.f;
        v.z = (cb + 2 >= s) ? acc[i][2] : 0.f;
        v.w = (cb + 3 >= s) ? acc[i][3] : 0.f;
        *(float4*)(gt + s*64 + cb) = v;
    }
}

// ---------------------------------------------------------------------------
// Kernel G3: St[n][p] = sum_l B[l][n] * (w[l]*X[l][p]), w=exp(tot-cs).
// Straight tiles only (32KB) -> 7 CTAs/SM.
// ---------------------------------------------------------------------------
__global__ void __launch_bounds__(128, 6) gemm3_kernel(
    const float* __restrict__ X, const float* __restrict__ A,
    const float* __restrict__ B)
{
    __shared__ float Bs[64*PADS];    // B straight [l][n]
    __shared__ float Xw[64*PADS];    // w*X straight [l][p]
    __shared__ float s_cs[64], s_w[64];

    const int c = blockIdx.x, h = blockIdx.y, b = blockIdx.z;
    const int bhc = (b*NH + h)*NC + c;
    const int tid = threadIdx.x;
    const int tx = tid & 15, ty = tid >> 4;
    const size_t base = ((size_t)((b*4096 + c*64)*NH + h))*64;
    const int col4 = tx*4;

    if (tid < 64) {
        float v = A[(size_t)(b*4096 + c*64 + tid)*NH + h];
        #pragma unroll
        for (int o = 1; o < 32; o <<= 1) {
            float t = __shfl_up_sync(0xffffffffu, v, o);
            if ((tid & 31) >= o) v += t;
        }
        s_cs[tid] = v;
    }
    __syncthreads();
    if (tid >= 32 && tid < 64) s_cs[tid] += s_cs[31];
    __syncthreads();
    if (tid < 64) s_w[tid] = __expf(s_cs[63] - s_cs[tid]);
    __syncthreads();

    #pragma unroll
    for (int i = 0; i < 8; i++) {
        const int row = i*8 + ty;
        const size_t g = base + (size_t)row*1024 + col4;
        *(float4*)(Bs + row*PADS + col4) = *(const float4*)(B + g);
        float4 xf = *(const float4*)(X + g);
        const float w = s_w[row];
        *(float4*)(Xw + row*PADS + col4) =
            make_float4(xf.x*w, xf.y*w, xf.z*w, xf.w*w);
    }
    __syncthreads();

    const int rb = ty*8, cb = col4;
    float acc[8][4] = {};
    #pragma unroll 4
    for (int k = 0; k < 64; k++) {
        float a[8], bb[4];
        *(float4*)(a)     = *(const float4*)(Bs + k*PADS + rb);
        *(float4*)(a + 4) = *(const float4*)(Bs + k*PADS + rb + 4);
        *(float4*)(bb)    = *(const float4*)(Xw + k*PADS + cb);
        #pragma unroll
        for (int i = 0; i < 8; i++)
            #pragma unroll
            for (int j = 0; j < 4; j++)
                acc[i][j] += a[i] * bb[j];
    }

    float* st = g_states + (size_t)bhc*4096;
    #pragma unroll
    for (int i = 0; i < 8; i++)
        *(float4*)(st + (rb+i)*64 + cb) =
            make_float4(acc[i][0], acc[i][1], acc[i][2], acc[i][3]);
}

// ---------------------------------------------------------------------------
// Pass 2: inter-chunk scan, in place. S_out[c] = S_before; S = e_c*(S + v_c).
// ---------------------------------------------------------------------------
__global__ void __launch_bounds__(128) pass2_kernel()
{
    __shared__ float se[NC];
    const int slice = blockIdx.x, bh = blockIdx.y;
    const int tid = threadIdx.x;

    if (tid < NC) se[tid] = __expf(g_tot[bh*NC + tid]);
    __syncthreads();

    float* p = g_states + (size_t)bh*NC*4096 + slice*512 + tid*4;
    float4 v[8];
    #pragma unroll
    for (int j = 0; j < 8; j++) v[j] = *(float4*)(p + (size_t)j*4096);

    float4 S = make_float4(0.f, 0.f, 0.f, 0.f);
    #pragma unroll 8
    for (int c = 0; c < NC; c++) {
        float4 cur = v[c & 7];
        *(float4*)(p + (size_t)c*4096) = S;           // state BEFORE chunk c
        const float e = se[c];
        S.x = e * (S.x + cur.x);
        S.y = e * (S.y + cur.y);
        S.z = e * (S.z + cur.z);
        S.w = e * (S.w + cur.w);
        if (c + 8 < NC) v[c & 7] = *(float4*)(p + (size_t)(c+8)*4096);
    }
}

// ---------------------------------------------------------------------------
// Pass 3: single fused k-loop, scalar FFMA:
//   Y[l][p] = sum_k Gt[k][l]*X[k][p] + sum_k Cte[k][l]*St[k][p]
// Gt streamed from g_G (L2-hot) with branchless reg double-buffer.
// 128 threads, 8x4 micro-tiles, 3 smem tiles (49KB) -> 4 CTAs/SM.
// ---------------------------------------------------------------------------
__global__ void __launch_bounds__(128, 4) pass3_kernel(
    const float* __restrict__ X, const float* __restrict__ A,
    const float* __restrict__ C, float* __restrict__ Y)
{
    extern __shared__ float sm[];
    float* Xs  = sm;                          // [64][PADS]
    float* Ss  = sm + 64*PADS;                // [64][PADS]
    float* Cte = sm + 2*64*PADS;              // [64][PADT] C^T * ecl
    __shared__ float s_cs[64], s_ecl[64];

    const int c = blockIdx.x, h = blockIdx.y, b = blockIdx.z;
    const int bhc = (b*NH + h)*NC + c;
    const int tid = threadIdx.x;
    const int tx = tid & 15, ty = tid >> 4;
    const size_t base = ((size_t)((b*4096 + c*64)*NH + h))*64;
    const float* Sg = g_states + (size_t)bhc*4096;
    const int col4 = tx*4;

    if (tid < 64) {
        float v = A[(size_t)(b*4096 + c*64 + tid)*NH + h];
        #pragma unroll
        for (int o = 1; o < 32; o <<= 1) {
            float t = __shfl_up_sync(0xffffffffu, v, o);
            if ((tid & 31) >= o) v += t;
        }
        s_cs[tid] = v;
    }
    __syncthreads();
    if (tid >= 32 && tid < 64) s_cs[tid] += s_cs[31];
    __syncthreads();
    if (tid < 64) s_ecl[tid] = __expf(s_cs[tid]);
    __syncthreads();

    #pragma unroll
    for (int i = 0; i < 8; i++) {
        const int row = i*8 + ty;
        *(float4*)(Xs + row*PADS + col4) =
            *(const float4*)(X + base + (size_t)row*1024 + col4);
        *(float4*)(Ss + row*PADS + col4) = *(const float4*)(Sg + row*64 + col4);
        float4 cf = *(const float4*)(C + base + (size_t)row*1024 + col4);
        const float e = s_ecl[row];
        float cs[4] = {cf.x*e, cf.y*e, cf.z*e, cf.w*e};
        #pragma unroll
        for (int q = 0; q < 4; q++) {
            const int eq = (q + (tx >> 1)) & 3;
            Cte[(col4 + eq)*PADT + row] = cs[eq];
        }
    }
    __syncthreads();

    const int rb = ty*8, cb = col4;

    float acc[8][4] = {};
    const float* gt = g_G + (size_t)bhc*4096;
    float4 ga = __ldg((const float4*)(gt + rb));
    float4 gb = __ldg((const float4*)(gt + rb + 4));
    #pragma unroll 4
    for (int k = 0; k < 64; k++) {
        const int kn = (k + 1) & 63;                 // branchless wrap prefetch
        float4 na = __ldg((const float4*)(gt + kn*64 + rb));
        float4 nb = __ldg((const float4*)(gt + kn*64 + rb + 4));
        float cf[8], gf[8];
        *(float4*)(cf)     = *(const float4*)(Cte + k*PADT + rb);
        *(float4*)(cf + 4) = *(const float4*)(Cte + k*PADT + rb + 4);
        *(float4*)(gf)     = ga;
        *(float4*)(gf + 4) = gb;
        float xb[4], sb[4];
        *(float4*)(xb) = *(const float4*)(Xs + k*PADS + cb);
        *(float4*)(sb) = *(const float4*)(Ss + k*PADS + cb);
        #pragma unroll
        for (int i = 0; i < 8; i++)
            #pragma unroll
            for (int j = 0; j < 4; j++)
                acc[i][j] += gf[i] * xb[j];
        #pragma unroll
        for (int i = 0; i < 8; i++)
            #pragma unroll
            for (int j = 0; j < 4; j++)
                acc[i][j] += cf[i] * sb[j];
        ga = na; gb = nb;
    }

    #pragma unroll
    for (int i = 0; i < 8; i++)
        *(float4*)(Y + base + (size_t)(rb+i)*1024 + cb) =
            make_float4(acc[i][0], acc[i][1], acc[i][2], acc[i][3]);
}

// ---------------------------------------------------------------------------
extern "C" void kernel_launch(void* const* d_in, const int* in_sizes, int n_in,
                              void* d_out, int out_size)
{
    const float* X = (const float*)d_in[0];
    const float* A = (const float*)d_in[1];
    const float* B = (const float*)d_in[2];
    const float* C = (const float*)d_in[3];
    float* Y = (float*)d_out;

    const int smem3 = (2*64*PADS + 64*PADT) * sizeof(float);    // 50,176 B
    cudaFuncSetAttribute(pass3_kernel,
                         cudaFuncAttributeMaxDynamicSharedMemorySize, smem3);

    dim3 grid(NC, NH, NB);
    gemm1_kernel<<<grid, 128>>>(A, B, C);
    gemm3_kernel<<<grid, 128>>>(X, A, B);
    pass2_kernel<<<dim3(8, NB*NH), 128>>>();
    pass3_kernel<<<grid, 128, smem3>>>(X, A, C, Y);
}

// round 9
// speedup vs baseline: 1.2050x; 1.2050x over previous
#include <cuda_runtime.h>

// Problem constants: b=2, s=4096, h=16, p=n=64, BLOCK_LEN=64
#define NB   2
#define NH   16
#define NC   64
#define PADS 64   // straight tiles
#define PADT 68   // transposed tiles (mult of 4; rotated stores <=2-way)

// Scratch (__device__ globals; allocation-free rule)
__device__ float g_states[NB*NH*NC*4096];  // chunk states [n][p]; scanned in place
__device__ float g_tot[NB*NH*NC];          // per-chunk A totals

// ---------------------------------------------------------------------------
// Kernel 1: St[n][p] = sum_l B[l][n] * (w[l]*X[l][p]),  w = exp(tot - cs).
// 128 threads, 8x4 micro-tile, 2 straight tiles (32KB) -> high occupancy.
// ---------------------------------------------------------------------------
__global__ void __launch_bounds__(128, 6) gemm3_kernel(
    const float* __restrict__ X, const float* __restrict__ A,
    const float* __restrict__ B)
{
    __shared__ float Bs[64*PADS];    // B straight [l][n]
    __shared__ float Xw[64*PADS];    // w*X straight [l][p]
    __shared__ float s_cs[64], s_w[64];

    const int c = blockIdx.x, h = blockIdx.y, b = blockIdx.z;
    const int bhc = (b*NH + h)*NC + c;
    const int tid = threadIdx.x;
    const int tx = tid & 15, ty = tid >> 4;
    const size_t base = ((size_t)((b*4096 + c*64)*NH + h))*64;
    const int col4 = tx*4;

    if (tid < 64) {
        float v = A[(size_t)(b*4096 + c*64 + tid)*NH + h];
        #pragma unroll
        for (int o = 1; o < 32; o <<= 1) {
            float t = __shfl_up_sync(0xffffffffu, v, o);
            if ((tid & 31) >= o) v += t;
        }
        s_cs[tid] = v;
    }
    __syncthreads();
    if (tid >= 32 && tid < 64) s_cs[tid] += s_cs[31];
    __syncthreads();
    if (tid < 64) {
        s_w[tid] = __expf(s_cs[63] - s_cs[tid]);
        if (tid == 63) g_tot[bhc] = s_cs[63];
    }
    __syncthreads();

    #pragma unroll
    for (int i = 0; i < 8; i++) {
        const int row = i*8 + ty;
        const size_t g = base + (size_t)row*1024 + col4;
        *(float4*)(Bs + row*PADS + col4) = *(const float4*)(B + g);
        float4 xf = *(const float4*)(X + g);
        const float w = s_w[row];
        *(float4*)(Xw + row*PADS + col4) =
            make_float4(xf.x*w, xf.y*w, xf.z*w, xf.w*w);
    }
    __syncthreads();

    const int rb = ty*8, cb = col4;
    float acc[8][4] = {};
    #pragma unroll 4
    for (int k = 0; k < 64; k++) {
        float a[8], bb[4];
        *(float4*)(a)     = *(const float4*)(Bs + k*PADS + rb);
        *(float4*)(a + 4) = *(const float4*)(Bs + k*PADS + rb + 4);
        *(float4*)(bb)    = *(const float4*)(Xw + k*PADS + cb);
        #pragma unroll
        for (int i = 0; i < 8; i++)
            #pragma unroll
            for (int j = 0; j < 4; j++)
                acc[i][j] += a[i] * bb[j];
    }

    float* st = g_states + (size_t)bhc*4096;
    #pragma unroll
    for (int i = 0; i < 8; i++)
        *(float4*)(st + (rb+i)*64 + cb) =
            make_float4(acc[i][0], acc[i][1], acc[i][2], acc[i][3]);
}

// ---------------------------------------------------------------------------
// Pass 2: inter-chunk scan, in place. S_out[c] = S_before; S = e_c*(S + v_c).
// ---------------------------------------------------------------------------
__global__ void __launch_bounds__(128) pass2_kernel()
{
    __shared__ float se[NC];
    const int slice = blockIdx.x, bh = blockIdx.y;
    const int tid = threadIdx.x;

    if (tid < NC) se[tid] = __expf(g_tot[bh*NC + tid]);
    __syncthreads();

    float* p = g_states + (size_t)bh*NC*4096 + slice*512 + tid*4;
    float4 v[8];
    #pragma unroll
    for (int j = 0; j < 8; j++) v[j] = *(float4*)(p + (size_t)j*4096);

    float4 S = make_float4(0.f, 0.f, 0.f, 0.f);
    #pragma unroll 8
    for (int c = 0; c < NC; c++) {
        float4 cur = v[c & 7];
        *(float4*)(p + (size_t)c*4096) = S;           // state BEFORE chunk c
        const float e = se[c];
        S.x = e * (S.x + cur.x);
        S.y = e * (S.y + cur.y);
        S.z = e * (S.z + cur.z);
        S.w = e * (S.w + cur.w);
        if (c + 8 < NC) v[c & 7] = *(float4*)(p + (size_t)(c+8)*4096);
    }
}

// ---------------------------------------------------------------------------
// Kernel 3 (3 GEMMs, G never leaves smem):
//   phase 1: Gt[s][l] = (l>=s) ? em[s]*sum_n Bt[n][s]*Cte[n][l] : 0  (in smem)
//   phase 2: Y[l][p]  = sum_s Gt[s][l]*X[s][p] + sum_n Cte[n][l]*Ss[n][p]
// 128 threads, 8x4 micro-tiles, scalar FFMA. smem 69.6KB -> 3 CTAs/SM.
// ---------------------------------------------------------------------------
__global__ void __launch_bounds__(128, 3) pass3_kernel(
    const float* __restrict__ X, const float* __restrict__ A,
    const float* __restrict__ B, const float* __restrict__ C,
    float* __restrict__ Y)
{
    extern __shared__ float sm[];
    float* Xs  = sm;                          // [64][PADS] X straight
    float* Ss  = sm + 64*PADS;                // [64][PADS] scanned S [n][p]
    float* Cte = sm + 2*64*PADS;              // [64][PADT] C^T * ecl
    float* BtG = sm + 2*64*PADS + 64*PADT;    // [64][PADT] B^T -> Gt
    __shared__ float s_cs[64], s_ecl[64], s_em[64];

    const int c = blockIdx.x, h = blockIdx.y, b = blockIdx.z;
    const int bhc = (b*NH + h)*NC + c;
    const int tid = threadIdx.x;
    const int tx = tid & 15, ty = tid >> 4;
    const size_t base = ((size_t)((b*4096 + c*64)*NH + h))*64;
    const float* Sg = g_states + (size_t)bhc*4096;
    const int col4 = tx*4;

    // cumsum of A
    if (tid < 64) {
        const float av = A[(size_t)(b*4096 + c*64 + tid)*NH + h];
        float v = av;
        #pragma unroll
        for (int o = 1; o < 32; o <<= 1) {
            float t = __shfl_up_sync(0xffffffffu, v, o);
            if ((tid & 31) >= o) v += t;
        }
        s_cs[tid] = v;
        s_em[tid] = av;   // stash A
    }
    __syncthreads();
    if (tid >= 32 && tid < 64) s_cs[tid] += s_cs[31];
    __syncthreads();
    if (tid < 64) {
        const float csl = s_cs[tid];
        s_ecl[tid] = __expf(csl);
        s_em[tid]  = __expf(s_em[tid] - csl);
    }
    __syncthreads();

    // loads: X, S straight; B -> BtG transposed; C -> Cte transposed*ecl
    #pragma unroll
    for (int i = 0; i < 8; i++) {
        const int row = i*8 + ty;
        const size_t g = base + (size_t)row*1024 + col4;
        *(float4*)(Xs + row*PADS + col4) = *(const float4*)(X + g);
        *(float4*)(Ss + row*PADS + col4) = *(const float4*)(Sg + row*64 + col4);
        float4 bf = *(const float4*)(B + g);
        float4 cf = *(const float4*)(C + g);
        const float e = s_ecl[row];
        float bs[4] = {bf.x, bf.y, bf.z, bf.w};
        float cs[4] = {cf.x*e, cf.y*e, cf.z*e, cf.w*e};
        #pragma unroll
        for (int q = 0; q < 4; q++) {
            const int eq = (q + (tx >> 1)) & 3;   // rotation: <=2-way conflicts
            BtG[(col4 + eq)*PADT + row] = bs[eq];
            Cte[(col4 + eq)*PADT + row] = cs[eq];
        }
    }
    __syncthreads();

    const int rb = ty*8, cb = col4;

    // ---- GEMM1: rows s=rb(8), cols l=cb(4); k=n ----
    {
        float acc[8][4] = {};
        #pragma unroll 4
        for (int k = 0; k < 64; k++) {
            float a[8], bb[4];
            *(float4*)(a)     = *(const float4*)(BtG + k*PADT + rb);
            *(float4*)(a + 4) = *(const float4*)(BtG + k*PADT + rb + 4);
            *(float4*)(bb)    = *(const float4*)(Cte + k*PADT + cb);
            #pragma unroll
            for (int i = 0; i < 8; i++)
                #pragma unroll
                for (int j = 0; j < 4; j++)
                    acc[i][j] += a[i] * bb[j];
        }
        __syncthreads();   // all GEMM1 reads of BtG complete -> overwrite with Gt
        #pragma unroll
        for (int i = 0; i < 8; i++) {
            const int s = rb + i;
            const float em = s_em[s];
            float4 v;
            v.x = (cb + 0 >= s) ? acc[i][0] * em : 0.f;
            v.y = (cb + 1 >= s) ? acc[i][1] * em : 0.f;
            v.z = (cb + 2 >= s) ? acc[i][2] * em : 0.f;
            v.w = (cb + 3 >= s) ? acc[i][3] * em : 0.f;
            *(float4*)(BtG + s*PADT + cb) = v;   // Gt[s][l], k(=s)-major
        }
    }
    __syncthreads();

    // ---- fused GEMM2+GEMM4: Y[l][p], rows l=rb(8), cols p=cb(4) ----
    float acc[8][4] = {};
    #pragma unroll 2
    for (int k = 0; k < 64; k++) {
        float gf[8], cf[8], xb[4], sb[4];
        *(float4*)(gf)     = *(const float4*)(BtG + k*PADT + rb);
        *(float4*)(gf + 4) = *(const float4*)(BtG + k*PADT + rb + 4);
        *(float4*)(cf)     = *(const float4*)(Cte + k*PADT + rb);
        *(float4*)(cf + 4) = *(const float4*)(Cte + k*PADT + rb + 4);
        *(float4*)(xb)     = *(const float4*)(Xs + k*PADS + cb);
        *(float4*)(sb)     = *(const float4*)(Ss + k*PADS + cb);
        #pragma unroll
        for (int i = 0; i < 8; i++)
            #pragma unroll
            for (int j = 0; j < 4; j++)
                acc[i][j] += gf[i] * xb[j];
        #pragma unroll
        for (int i = 0; i < 8; i++)
            #pragma unroll
            for (int j = 0; j < 4; j++)
                acc[i][j] += cf[i] * sb[j];
    }

    #pragma unroll
    for (int i = 0; i < 8; i++)
        *(float4*)(Y + base + (size_t)(rb+i)*1024 + cb) =
            make_float4(acc[i][0], acc[i][1], acc[i][2], acc[i][3]);
}

// ---------------------------------------------------------------------------
extern "C" void kernel_launch(void* const* d_in, const int* in_sizes, int n_in,
                              void* d_out, int out_size)
{
    const float* X = (const float*)d_in[0];
    const float* A = (const float*)d_in[1];
    const float* B = (const float*)d_in[2];
    const float* C = (const float*)d_in[3];
    float* Y = (float*)d_out;

    const int smem3 = (2*64*PADS + 2*64*PADT) * sizeof(float);  // 69,632 B
    cudaFuncSetAttribute(pass3_kernel,
                         cudaFuncAttributeMaxDynamicSharedMemorySize, smem3);

    dim3 grid(NC, NH, NB);
    gemm3_kernel<<<grid, 128>>>(X, A, B);
    pass2_kernel<<<dim3(8, NB*NH), 128>>>();
    pass3_kernel<<<grid, 128, smem3>>>(X, A, B, C, Y);
}

// round 10
// speedup vs baseline: 1.5727x; 1.3051x over previous
#include <cuda_runtime.h>
#include <cuda_bf16.h>

// Problem constants: b=2, s=4096, h=16, p=n=64, BLOCK_LEN=64
#define NB   2
#define NH   16
#define NC   64
#define PADS 64    // scalar straight tiles (gemm3)
#define PB   144   // bf16 tile row pitch in BYTES (72 bf16 = 64 + 8 pad)

// bf16 tile byte offsets inside pass3 dynamic smem
#define OFF_BH 0
#define OFF_BL 9216
#define OFF_CH 18432
#define OFF_CL 27648
#define OFF_XH 36864
#define OFF_XL 46080
#define OFF_SH 55296
#define OFF_SL 64512
#define SMEM3  73728
// G tiles overwrite the dead B tiles after GEMM1
#define OFF_GH OFF_BH
#define OFF_GL OFF_BL

// Scratch (__device__ globals; allocation-free rule)
__device__ float g_states[NB*NH*NC*4096];  // chunk states [p][n]; scanned in place
__device__ float g_tot[NB*NH*NC];          // per-chunk A totals

#define MMA_BF16(d, a0, a1, a2, a3, b0, b1)                               \
    asm("mma.sync.aligned.m16n8k16.row.col.f32.bf16.bf16.f32 "            \
        "{%0,%1,%2,%3}, {%4,%5,%6,%7}, {%8,%9}, {%0,%1,%2,%3};"           \
        : "+f"(d[0]), "+f"(d[1]), "+f"(d[2]), "+f"(d[3])                  \
        : "r"(a0), "r"(a1), "r"(a2), "r"(a3), "r"(b0), "r"(b1))

__device__ __forceinline__ void split1(float v, __nv_bfloat16& h, __nv_bfloat16& l) {
    h = __float2bfloat16(v);
    l = __float2bfloat16(v - __bfloat162float(h));
}
// split a float4 and store 4 hi bf16 + 4 lo bf16 (k-contiguous)
__device__ __forceinline__ void split4_store(float4 v, char* hp, char* lp) {
    __nv_bfloat16 h0,h1,h2,h3,l0,l1,l2,l3;
    split1(v.x,h0,l0); split1(v.y,h1,l1); split1(v.z,h2,l2); split1(v.w,h3,l3);
    __nv_bfloat162 a; a.x=h0; a.y=h1; *(__nv_bfloat162*)(hp)   = a;
    __nv_bfloat162 b; b.x=h2; b.y=h3; *(__nv_bfloat162*)(hp+4) = b;
    __nv_bfloat162 c; c.x=l0; c.y=l1; *(__nv_bfloat162*)(lp)   = c;
    __nv_bfloat162 d; d.x=l2; d.y=l3; *(__nv_bfloat162*)(lp+4) = d;
}

// ---------------------------------------------------------------------------
// Kernel 1 (scalar): S'[p][n] = sum_l (w[l]*X[l][p]) * B[l][n], w=exp(tot-cs).
// NOTE output layout [p][n] (k-contiguous for pass3's GEMM4 B-operand).
// ---------------------------------------------------------------------------
__global__ void __launch_bounds__(128, 6) gemm3_kernel(
    const float* __restrict__ X, const float* __restrict__ A,
    const float* __restrict__ B)
{
    __shared__ float Bs[64*PADS];    // B straight [l][n]
    __shared__ float Xw[64*PADS];    // w*X straight [l][p]
    __shared__ float s_cs[64], s_w[64];

    const int c = blockIdx.x, h = blockIdx.y, b = blockIdx.z;
    const int bhc = (b*NH + h)*NC + c;
    const int tid = threadIdx.x;
    const int tx = tid & 15, ty = tid >> 4;
    const size_t base = ((size_t)((b*4096 + c*64)*NH + h))*64;
    const int col4 = tx*4;

    if (tid < 64) {
        float v = A[(size_t)(b*4096 + c*64 + tid)*NH + h];
        #pragma unroll
        for (int o = 1; o < 32; o <<= 1) {
            float t = __shfl_up_sync(0xffffffffu, v, o);
            if ((tid & 31) >= o) v += t;
        }
        s_cs[tid] = v;
    }
    __syncthreads();
    if (tid >= 32 && tid < 64) s_cs[tid] += s_cs[31];
    __syncthreads();
    if (tid < 64) {
        s_w[tid] = __expf(s_cs[63] - s_cs[tid]);
        if (tid == 63) g_tot[bhc] = s_cs[63];
    }
    __syncthreads();

    #pragma unroll
    for (int i = 0; i < 8; i++) {
        const int row = i*8 + ty;
        const size_t g = base + (size_t)row*1024 + col4;
        *(float4*)(Bs + row*PADS + col4) = *(const float4*)(B + g);
        float4 xf = *(const float4*)(X + g);
        const float w = s_w[row];
        *(float4*)(Xw + row*PADS + col4) =
            make_float4(xf.x*w, xf.y*w, xf.z*w, xf.w*w);
    }
    __syncthreads();

    const int rb = ty*8, cb = col4;   // rb over p, cb over n
    float acc[8][4] = {};
    #pragma unroll 4
    for (int k = 0; k < 64; k++) {
        float a[8], bb[4];
        *(float4*)(a)     = *(const float4*)(Xw + k*PADS + rb);
        *(float4*)(a + 4) = *(const float4*)(Xw + k*PADS + rb + 4);
        *(float4*)(bb)    = *(const float4*)(Bs + k*PADS + cb);
        #pragma unroll
        for (int i = 0; i < 8; i++)
            #pragma unroll
            for (int j = 0; j < 4; j++)
                acc[i][j] += a[i] * bb[j];
    }

    float* st = g_states + (size_t)bhc*4096;   // [p][n]
    #pragma unroll
    for (int i = 0; i < 8; i++)
        *(float4*)(st + (rb+i)*64 + cb) =
            make_float4(acc[i][0], acc[i][1], acc[i][2], acc[i][3]);
}

// ---------------------------------------------------------------------------
// Pass 2: inter-chunk scan, in place (elementwise; layout-agnostic).
// ---------------------------------------------------------------------------
__global__ void __launch_bounds__(128) pass2_kernel()
{
    __shared__ float se[NC];
    const int slice = blockIdx.x, bh = blockIdx.y;
    const int tid = threadIdx.x;

    if (tid < NC) se[tid] = __expf(g_tot[bh*NC + tid]);
    __syncthreads();

    float* p = g_states + (size_t)bh*NC*4096 + slice*512 + tid*4;
    float4 v[8];
    #pragma unroll
    for (int j = 0; j < 8; j++) v[j] = *(float4*)(p + (size_t)j*4096);

    float4 S = make_float4(0.f, 0.f, 0.f, 0.f);
    #pragma unroll 8
    for (int c = 0; c < NC; c++) {
        float4 cur = v[c & 7];
        *(float4*)(p + (size_t)c*4096) = S;
        const float e = se[c];
        S.x = e * (S.x + cur.x);
        S.y = e * (S.y + cur.y);
        S.z = e * (S.z + cur.z);
        S.w = e * (S.w + cur.w);
        if (c + 8 < NC) v[c & 7] = *(float4*)(p + (size_t)(c+8)*4096);
    }
}

// ---------------------------------------------------------------------------
// Pass 3 (tensor cores, bf16 2-term split):
//  GEMM1: D[s][l] = sum_n B[s][n]*C[l][n]; epi: mask l>=s, *em[s], split -> G[l][s]
//  GEMM2+4: acc[l][p] = sum_s G[l][s]*Xt[p][s] + sum_n C[l][n]*S'[p][n]
//  final: Y[l][p] = ecl[l]*acc
// 128 threads (4 warps; warp w owns 16 output rows), 3 CTAs/SM.
// ---------------------------------------------------------------------------
__global__ void __launch_bounds__(128, 3) pass3_kernel(
    const float* __restrict__ X, const float* __restrict__ A,
    const float* __restrict__ B, const float* __restrict__ C,
    float* __restrict__ Y)
{
    extern __shared__ char smem[];
    __shared__ float s_cs[64], s_ecl[64], s_em[64];

    const int c = blockIdx.x, h = blockIdx.y, b = blockIdx.z;
    const int bhc = (b*NH + h)*NC + c;
    const int tid = threadIdx.x;
    const int tx = tid & 15, ty = tid >> 4;
    const size_t base = ((size_t)((b*4096 + c*64)*NH + h))*64;
    const float* Sg = g_states + (size_t)bhc*4096;
    const int col4 = tx*4;

    // cumsum of A
    if (tid < 64) {
        const float av = A[(size_t)(b*4096 + c*64 + tid)*NH + h];
        float v = av;
        #pragma unroll
        for (int o = 1; o < 32; o <<= 1) {
            float t = __shfl_up_sync(0xffffffffu, v, o);
            if ((tid & 31) >= o) v += t;
        }
        s_cs[tid] = v;
        s_em[tid] = av;   // stash A
    }

    // load + bf16-split all operand tiles
    #pragma unroll
    for (int i = 0; i < 8; i++) {
        const int row = i*8 + ty;
        const size_t g = base + (size_t)row*1024 + col4;
        float4 bf = *(const float4*)(B + g);
        float4 cf = *(const float4*)(C + g);
        float4 xf = *(const float4*)(X + g);
        float4 sf = *(const float4*)(Sg + row*64 + col4);
        split4_store(bf, smem + OFF_BH + row*PB + col4*2,
                         smem + OFF_BL + row*PB + col4*2);
        split4_store(cf, smem + OFF_CH + row*PB + col4*2,
                         smem + OFF_CL + row*PB + col4*2);
        split4_store(sf, smem + OFF_SH + row*PB + col4*2,
                         smem + OFF_SL + row*PB + col4*2);
        // X transposed: Xt[p][s], scattered 16-bit stores
        const float xv[4] = {xf.x, xf.y, xf.z, xf.w};
        #pragma unroll
        for (int q = 0; q < 4; q++) {
            __nv_bfloat16 hq, lq;
            split1(xv[q], hq, lq);
            *(__nv_bfloat16*)(smem + OFF_XH + (col4+q)*PB + row*2) = hq;
            *(__nv_bfloat16*)(smem + OFF_XL + (col4+q)*PB + row*2) = lq;
        }
    }
    __syncthreads();
    if (tid >= 32 && tid < 64) s_cs[tid] += s_cs[31];
    __syncthreads();
    if (tid < 64) {
        const float csl = s_cs[tid];
        s_ecl[tid] = __expf(csl);
        s_em[tid]  = __expf(s_em[tid] - csl);
    }
    __syncthreads();

    const int w = tid >> 5, lane = tid & 31;
    const int gq = lane >> 2, t4 = lane & 3;
    const int r0 = 16*w + gq;                // A-frag row (s in GEMM1, l in GEMM2+4)

    unsigned ah[16], al[16];
    float acc[8][4];

    // ---- GEMM1: A=B[s][n], Bop=C[l][n]; D[s][l] ----
    #pragma unroll
    for (int nt = 0; nt < 8; nt++)
        #pragma unroll
        for (int j = 0; j < 4; j++) acc[nt][j] = 0.f;
    #pragma unroll
    for (int kt = 0; kt < 4; kt++) {
        const int kb = (kt*16 + 2*t4)*2;
        ah[kt*4+0] = *(const unsigned*)(smem + OFF_BH + (r0  )*PB + kb);
        ah[kt*4+1] = *(const unsigned*)(smem + OFF_BH + (r0+8)*PB + kb);
        ah[kt*4+2] = *(const unsigned*)(smem + OFF_BH + (r0  )*PB + kb + 16);
        ah[kt*4+3] = *(const unsigned*)(smem + OFF_BH + (r0+8)*PB + kb + 16);
        al[kt*4+0] = *(const unsigned*)(smem + OFF_BL + (r0  )*PB + kb);
        al[kt*4+1] = *(const unsigned*)(smem + OFF_BL + (r0+8)*PB + kb);
        al[kt*4+2] = *(const unsigned*)(smem + OFF_BL + (r0  )*PB + kb + 16);
        al[kt*4+3] = *(const unsigned*)(smem + OFF_BL + (r0+8)*PB + kb + 16);
    }
    #pragma unroll
    for (int nt = 0; nt < 8; nt++) {
        #pragma unroll
        for (int kt = 0; kt < 4; kt++) {
            const int kb = (kt*16 + 2*t4)*2;
            const char* pr = smem + (nt*8 + gq)*PB + kb;
            unsigned bh0 = *(const unsigned*)(pr + OFF_CH);
            unsigned bh1 = *(const unsigned*)(pr + OFF_CH + 16);
            unsigned bl0 = *(const unsigned*)(pr + OFF_CL);
            unsigned bl1 = *(const unsigned*)(pr + OFF_CL + 16);
            MMA_BF16(acc[nt], ah[kt*4+0], ah[kt*4+1], ah[kt*4+2], ah[kt*4+3], bh0, bh1);
            MMA_BF16(acc[nt], ah[kt*4+0], ah[kt*4+1], ah[kt*4+2], ah[kt*4+3], bl0, bl1);
            MMA_BF16(acc[nt], al[kt*4+0], al[kt*4+1], al[kt*4+2], al[kt*4+3], bh0, bh1);
        }
    }
    __syncthreads();   // all GEMM1 smem reads done -> B tiles reusable as G

    // epilogue: mask + em scale, split, store G[l][s] over B tiles
    {
        const int s0 = r0, s1 = r0 + 8;
        const float em0 = s_em[s0], em1 = s_em[s1];
        #pragma unroll
        for (int nt = 0; nt < 8; nt++) {
            const int l0 = nt*8 + 2*t4, l1 = l0 + 1;
            float v00 = (l0 >= s0) ? acc[nt][0]*em0 : 0.f;
            float v01 = (l1 >= s0) ? acc[nt][1]*em0 : 0.f;
            float v10 = (l0 >= s1) ? acc[nt][2]*em1 : 0.f;
            float v11 = (l1 >= s1) ? acc[nt][3]*em1 : 0.f;
            __nv_bfloat16 hh, ll;
            split1(v00, hh, ll);
            *(__nv_bfloat16*)(smem + OFF_GH + l0*PB + s0*2) = hh;
            *(__nv_bfloat16*)(smem + OFF_GL + l0*PB + s0*2) = ll;
            split1(v01, hh, ll);
            *(__nv_bfloat16*)(smem + OFF_GH + l1*PB + s0*2) = hh;
            *(__nv_bfloat16*)(smem + OFF_GL + l1*PB + s0*2) = ll;
            split1(v10, hh, ll);
            *(__nv_bfloat16*)(smem + OFF_GH + l0*PB + s1*2) = hh;
            *(__nv_bfloat16*)(smem + OFF_GL + l0*PB + s1*2) = ll;
            split1(v11, hh, ll);
            *(__nv_bfloat16*)(smem + OFF_GH + l1*PB + s1*2) = hh;
            *(__nv_bfloat16*)(smem + OFF_GL + l1*PB + s1*2) = ll;
        }
    }
    __syncthreads();

    // ---- fused GEMM2+GEMM4: D[l][p] ----
    #pragma unroll
    for (int nt = 0; nt < 8; nt++)
        #pragma unroll
        for (int j = 0; j < 4; j++) acc[nt][j] = 0.f;

    // phase A: A=G[l][s], Bop=Xt[p][s]
    #pragma unroll
    for (int kt = 0; kt < 4; kt++) {
        const int kb = (kt*16 + 2*t4)*2;
        ah[kt*4+0] = *(const unsigned*)(smem + OFF_GH + (r0  )*PB + kb);
        ah[kt*4+1] = *(const unsigned*)(smem + OFF_GH + (r0+8)*PB + kb);
        ah[kt*4+2] = *(const unsigned*)(smem + OFF_GH + (r0  )*PB + kb + 16);
        ah[kt*4+3] = *(const unsigned*)(smem + OFF_GH + (r0+8)*PB + kb + 16);
        al[kt*4+0] = *(const unsigned*)(smem + OFF_GL + (r0  )*PB + kb);
        al[kt*4+1] = *(const unsigned*)(smem + OFF_GL + (r0+8)*PB + kb);
        al[kt*4+2] = *(const unsigned*)(smem + OFF_GL + (r0  )*PB + kb + 16);
        al[kt*4+3] = *(const unsigned*)(smem + OFF_GL + (r0+8)*PB + kb + 16);
    }
    #pragma unroll
    for (int nt = 0; nt < 8; nt++) {
        #pragma unroll
        for (int kt = 0; kt < 4; kt++) {
            const int kb = (kt*16 + 2*t4)*2;
            const char* pr = smem + (nt*8 + gq)*PB + kb;
            unsigned bh0 = *(const unsigned*)(pr + OFF_XH);
            unsigned bh1 = *(const unsigned*)(pr + OFF_XH + 16);
            unsigned bl0 = *(const unsigned*)(pr + OFF_XL);
            unsigned bl1 = *(const unsigned*)(pr + OFF_XL + 16);
            MMA_BF16(acc[nt], ah[kt*4+0], ah[kt*4+1], ah[kt*4+2], ah[kt*4+3], bh0, bh1);
            MMA_BF16(acc[nt], ah[kt*4+0], ah[kt*4+1], ah[kt*4+2], ah[kt*4+3], bl0, bl1);
            MMA_BF16(acc[nt], al[kt*4+0], al[kt*4+1], al[kt*4+2], al[kt*4+3], bh0, bh1);
        }
    }
    // phase B: A=C[l][n], Bop=S'[p][n]
    #pragma unroll
    for (int kt = 0; kt < 4; kt++) {
        const int kb = (kt*16 + 2*t4)*2;
        ah[kt*4+0] = *(const unsigned*)(smem + OFF_CH + (r0  )*PB + kb);
        ah[kt*4+1] = *(const unsigned*)(smem + OFF_CH + (r0+8)*PB + kb);
        ah[kt*4+2] = *(const unsigned*)(smem + OFF_CH + (r0  )*PB + kb + 16);
        ah[kt*4+3] = *(const unsigned*)(smem + OFF_CH + (r0+8)*PB + kb + 16);
        al[kt*4+0] = *(const unsigned*)(smem + OFF_CL + (r0  )*PB + kb);
        al[kt*4+1] = *(const unsigned*)(smem + OFF_CL + (r0+8)*PB + kb);
        al[kt*4+2] = *(const unsigned*)(smem + OFF_CL + (r0  )*PB + kb + 16);
        al[kt*4+3] = *(const unsigned*)(smem + OFF_CL + (r0+8)*PB + kb + 16);
    }
    #pragma unroll
    for (int nt = 0; nt < 8; nt++) {
        #pragma unroll
        for (int kt = 0; kt < 4; kt++) {
            const int kb = (kt*16 + 2*t4)*2;
            const char* pr = smem + (nt*8 + gq)*PB + kb;
            unsigned bh0 = *(const unsigned*)(pr + OFF_SH);
            unsigned bh1 = *(const unsigned*)(pr + OFF_SH + 16);
            unsigned bl0 = *(const unsigned*)(pr + OFF_SL);
            unsigned bl1 = *(const unsigned*)(pr + OFF_SL + 16);
            MMA_BF16(acc[nt], ah[kt*4+0], ah[kt*4+1], ah[kt*4+2], ah[kt*4+3], bh0, bh1);
            MMA_BF16(acc[nt], ah[kt*4+0], ah[kt*4+1], ah[kt*4+2], ah[kt*4+3], bl0, bl1);
            MMA_BF16(acc[nt], al[kt*4+0], al[kt*4+1], al[kt*4+2], al[kt*4+3], bh0, bh1);
        }
    }

    // final: Y[l][p] = ecl[l] * acc
    {
        const int l0 = r0, l1 = r0 + 8;
        const float e0 = s_ecl[l0], e1 = s_ecl[l1];
        #pragma unroll
        for (int nt = 0; nt < 8; nt++) {
            const int p0 = nt*8 + 2*t4;
            *(float2*)(Y + base + (size_t)l0*1024 + p0) =
                make_float2(e0*acc[nt][0], e0*acc[nt][1]);
            *(float2*)(Y + base + (size_t)l1*1024 + p0) =
                make_float2(e1*acc[nt][2], e1*acc[nt][3]);
        }
    }
}

// ---------------------------------------------------------------------------
extern "C" void kernel_launch(void* const* d_in, const int* in_sizes, int n_in,
                              void* d_out, int out_size)
{
    const float* X = (const float*)d_in[0];
    const float* A = (const float*)d_in[1];
    const float* B = (const float*)d_in[2];
    const float* C = (const float*)d_in[3];
    float* Y = (float*)d_out;

    cudaFuncSetAttribute(pass3_kernel,
                         cudaFuncAttributeMaxDynamicSharedMemorySize, SMEM3);

    dim3 grid(NC, NH, NB);
    gemm3_kernel<<<grid, 128>>>(X, A, B);
    pass2_kernel<<<dim3(8, NB*NH), 128>>>();
    pass3_kernel<<<grid, 128, SMEM3>>>(X, A, B, C, Y);
}